// round 14
// baseline (speedup 1.0000x reference)
#include <cuda_runtime.h>
#include <cstdint>

// ============================================================================
// InstantNerf fused MLP, warp-level mma.sync fp16 (m16n8k16, fp32 acc), sm_103.
// R13: R12 + 64-sample warp tiles (4 m16-tiles/warp). One B-fragment pair
// load now feeds 8 MMAs (4m x 2n), halving weight LDG bytes/sample and
// quadrupling independent MMA chains. Activations stay register-resident
// (D-fragment layout == next layer's A-fragment layout); only SH crosses smem.
//  - CTA = 128 threads = 4 warps; warp owns 64 rows; CTA covers 256 rows.
//  - n-pair-outer / k-inner loops bound live acc to 32 floats.
// ============================================================================

static constexpr int THREADS = 128;
static constexpr int ROWS = 256;               // per CTA (64 per warp)
static constexpr int SHW = 12;   // SH row stride (words); (12g+tg) mod 32 all distinct

// smem word offsets
static constexpr int OFF_B1 = 0;      // 64 f32
static constexpr int OFF_B2 = 64;     // 16
static constexpr int OFF_B3 = 80;     // 64
static constexpr int OFF_B4 = 144;    // 64
static constexpr int OFF_B5 = 208;    // 8 (padded)
static constexpr int OFF_SH = 216;                     // 256*12 = 3072
static constexpr int SMEM_WORDS = OFF_SH + ROWS * SHW; // 3288 -> 13152 B

// global fragment buffer (word offsets); slot s = ks16*NTtot + ntile, 64 words
static constexpr int W1F = 0;       // 2k x 8n x 64 = 1024
static constexpr int W2F = 1024;    // 4k x 2n x 64 = 512
static constexpr int W3F = 1536;    // 2k x 8n x 64 = 1024
static constexpr int W4F = 2560;    // 4k x 8n x 64 = 2048
static constexpr int W5F = 4608;    // 4k x 1n x 64 = 256
__device__ uint32_t g_wfrag[4864];

__device__ __forceinline__ uint32_t h2pack(float lo, float hi) {
    uint32_t r;
    asm("cvt.rn.f16x2.f32 %0, %1, %2;" : "=r"(r) : "f"(hi), "f"(lo));
    return r;
}

__device__ __forceinline__ void mma_f16(float (&d)[4], uint32_t a0, uint32_t a1,
                                        uint32_t a2, uint32_t a3,
                                        uint32_t b0, uint32_t b1) {
    asm volatile(
        "mma.sync.aligned.m16n8k16.row.col.f32.f16.f16.f32 "
        "{%0,%1,%2,%3}, {%4,%5,%6,%7}, {%8,%9}, {%0,%1,%2,%3};"
        : "+f"(d[0]), "+f"(d[1]), "+f"(d[2]), "+f"(d[3])
        : "r"(a0), "r"(a1), "r"(a2), "r"(a3), "r"(b0), "r"(b1));
}

// ---------------- prep kernel: W[K][Nreal] -> f16x2 B-fragment order --------
__device__ __forceinline__ void stage_section(uint32_t* dst, const float* W,
                                              int Nreal, int KT, int NT,
                                              int tid, int ntot) {
    int total = KT * NT * 64;
    for (int idx = tid; idx < total; idx += ntot) {
        int s = idx >> 6, rem = idx & 63;
        int lane = rem >> 1, half = rem & 1;
        int ks = s / NT, nt = s - ks * NT;
        int g = lane >> 2, tg = lane & 3;
        int k0 = ks * 16 + half * 8 + 2 * tg;
        int nn = nt * 8 + g;
        float v0 = (nn < Nreal) ? W[k0 * Nreal + nn] : 0.0f;
        float v1 = (nn < Nreal) ? W[(k0 + 1) * Nreal + nn] : 0.0f;
        dst[s * 64 + lane * 2 + half] = h2pack(v0, v1);
    }
}

__global__ void prep_kernel(const float* __restrict__ W1, const float* __restrict__ W2,
                            const float* __restrict__ W3, const float* __restrict__ W4,
                            const float* __restrict__ W5) {
    int tid = blockIdx.x * blockDim.x + threadIdx.x;
    int ntot = gridDim.x * blockDim.x;
    stage_section(g_wfrag + W1F, W1, 64, 2, 8, tid, ntot);
    stage_section(g_wfrag + W2F, W2, 16, 4, 2, tid, ntot);
    stage_section(g_wfrag + W3F, W3, 64, 2, 8, tid, ntot);
    stage_section(g_wfrag + W4F, W4, 64, 4, 8, tid, ntot);
    stage_section(g_wfrag + W5F, W5, 3, 4, 1, tid, ntot);
}

// ---------------- layer core: 4 m-tiles, n-pair outer, relu output --------
template <int KT, int NPAIRS, int NTTOT>
__device__ __forceinline__ void layer_pairs(const uint32_t (&A)[4][KT][4],
                                            const uint2* __restrict__ bfrag,
                                            const float* __restrict__ bias,
                                            int tg, int lane,
                                            uint32_t (&Aout)[4][NPAIRS][4]) {
#pragma unroll
    for (int np = 0; np < NPAIRS; np++) {
        float acc[4][2][4];
#pragma unroll
        for (int mt = 0; mt < 4; mt++)
#pragma unroll
            for (int h = 0; h < 2; h++) {
                float2 bb = ((const float2*)bias)[(2 * np + h) * 4 + tg];
                acc[mt][h][0] = bb.x; acc[mt][h][1] = bb.y;
                acc[mt][h][2] = bb.x; acc[mt][h][3] = bb.y;
            }
#pragma unroll
        for (int k = 0; k < KT; k++) {
            uint2 bf0 = bfrag[(k * NTTOT + 2 * np) * 32 + lane];
            uint2 bf1 = bfrag[(k * NTTOT + 2 * np + 1) * 32 + lane];
#pragma unroll
            for (int mt = 0; mt < 4; mt++) {
                mma_f16(acc[mt][0], A[mt][k][0], A[mt][k][1], A[mt][k][2], A[mt][k][3],
                        bf0.x, bf0.y);
                mma_f16(acc[mt][1], A[mt][k][0], A[mt][k][1], A[mt][k][2], A[mt][k][3],
                        bf1.x, bf1.y);
            }
        }
#pragma unroll
        for (int mt = 0; mt < 4; mt++) {
            Aout[mt][np][0] = h2pack(fmaxf(acc[mt][0][0], 0.0f), fmaxf(acc[mt][0][1], 0.0f));
            Aout[mt][np][1] = h2pack(fmaxf(acc[mt][0][2], 0.0f), fmaxf(acc[mt][0][3], 0.0f));
            Aout[mt][np][2] = h2pack(fmaxf(acc[mt][1][0], 0.0f), fmaxf(acc[mt][1][1], 0.0f));
            Aout[mt][np][3] = h2pack(fmaxf(acc[mt][1][2], 0.0f), fmaxf(acc[mt][1][3], 0.0f));
        }
    }
}

__global__ void __launch_bounds__(THREADS, 3)
nerf_mma_kernel(const float* __restrict__ position,
                const float* __restrict__ direction,
                const float* __restrict__ b1, const float* __restrict__ b2,
                const float* __restrict__ b3, const float* __restrict__ b4,
                const float* __restrict__ b5,
                float* __restrict__ out, int n) {
    extern __shared__ float smf[];
    uint32_t* smu = (uint32_t*)smf;

    const int tid = threadIdx.x;
    const int lane = tid & 31;
    const int wid = tid >> 5;
    const int g = lane >> 2;
    const int tg = lane & 3;

    // biases (fp32)
    if (tid < 64) smf[OFF_B1 + tid] = b1[tid];
    if (tid < 16) smf[OFF_B2 + tid] = b2[tid];
    if (tid < 64) smf[OFF_B3 + tid] = b3[tid];
    if (tid < 64) smf[OFF_B4 + tid] = b4[tid];
    if (tid < 8)  smf[OFF_B5 + tid] = (tid < 3) ? b5[tid] : 0.0f;

    const int base = blockIdx.x * ROWS;
    uint32_t* SH = smu + OFF_SH;

    // ---- SH(dir) for rows tid and tid+128 -> SH buffer (stride 12) ----
#pragma unroll
    for (int rr = 0; rr < 2; rr++) {
        int row = tid + rr * 128;
        int r = base + row; if (r >= n) r = n - 1;
        const float* dp = direction + (size_t)r * 3;
        float x = dp[0], y = dp[1], z = dp[2];
        float xx = x * x, yy = y * y, zz = z * z;
        float sh[16];
        sh[0]  = 0.28209479177387814f;
        sh[1]  = 0.4886025119029199f * y;
        sh[2]  = 0.4886025119029199f * z;
        sh[3]  = 0.4886025119029199f * x;
        sh[4]  = 1.0925484305920792f * x * y;
        sh[5]  = 1.0925484305920792f * y * z;
        sh[6]  = 0.9461746957575601f * zz - 0.31539156525252f;
        sh[7]  = 1.0925484305920792f * x * z;
        sh[8]  = 0.5462742152960396f * (xx - yy);
        sh[9]  = 0.5900435899266435f * y * (3.0f * xx - yy);
        sh[10] = 2.890611442640554f * x * y * z;
        sh[11] = 0.4570457994644658f * y * (5.0f * zz - 1.0f);
        sh[12] = 0.3731763325901154f * z * (5.0f * zz - 3.0f);
        sh[13] = 0.4570457994644658f * x * (5.0f * zz - 1.0f);
        sh[14] = 1.445305721320277f * z * (xx - yy);
        sh[15] = 0.5900435899266435f * x * (xx - 3.0f * yy);
        uint32_t* rowp = SH + row * SHW;
#pragma unroll
        for (int j = 0; j < 8; j++) rowp[j] = h2pack(sh[2 * j], sh[2 * j + 1]);
    }
    __syncthreads();   // biases + SH visible

    const int mrow0 = wid * 64;
    const uint2* fr = (const uint2*)g_wfrag;

    // ---- L1 input: pos A-fragments for 4 m-tiles (K=32 -> 2 k-steps) ----
    uint32_t A[4][4][4];           // reused across layers (max KT=4)
    {
        uint32_t A1[4][2][4];
#pragma unroll
        for (int mt = 0; mt < 4; mt++) {
            int ra = base + mrow0 + mt * 16 + g;      if (ra >= n) ra = n - 1;
            int rb = base + mrow0 + mt * 16 + 8 + g;  if (rb >= n) rb = n - 1;
            const float* pa = position + (size_t)ra * 32 + 2 * tg;
            const float* pb = position + (size_t)rb * 32 + 2 * tg;
#pragma unroll
            for (int k = 0; k < 2; k++) {
                float2 v0 = *(const float2*)(pa + k * 16);
                float2 v1 = *(const float2*)(pb + k * 16);
                float2 v2 = *(const float2*)(pa + k * 16 + 8);
                float2 v3 = *(const float2*)(pb + k * 16 + 8);
                A1[mt][k][0] = h2pack(v0.x, v0.y);
                A1[mt][k][1] = h2pack(v1.x, v1.y);
                A1[mt][k][2] = h2pack(v2.x, v2.y);
                A1[mt][k][3] = h2pack(v3.x, v3.y);
            }
        }
        // ---- L1: pos @ W1 -> A (relu) ----
        layer_pairs<2, 4, 8>(A1, fr + (W1F >> 1), smf + OFF_B1, tg, lane, A);
    }

    // ---- L2: A @ W2 -> density; gmem fp32 + AD pack (no relu) ----
    uint32_t AD[4][4];
    {
        float acc2[4][2][4];
#pragma unroll
        for (int mt = 0; mt < 4; mt++)
#pragma unroll
            for (int h = 0; h < 2; h++) {
                float2 bb = ((const float2*)(smf + OFF_B2))[h * 4 + tg];
                acc2[mt][h][0] = bb.x; acc2[mt][h][1] = bb.y;
                acc2[mt][h][2] = bb.x; acc2[mt][h][3] = bb.y;
            }
#pragma unroll
        for (int k = 0; k < 4; k++) {
            uint2 bf0 = fr[(W2F >> 1) + (k * 2 + 0) * 32 + lane];
            uint2 bf1 = fr[(W2F >> 1) + (k * 2 + 1) * 32 + lane];
#pragma unroll
            for (int mt = 0; mt < 4; mt++) {
                mma_f16(acc2[mt][0], A[mt][k][0], A[mt][k][1], A[mt][k][2], A[mt][k][3],
                        bf0.x, bf0.y);
                mma_f16(acc2[mt][1], A[mt][k][0], A[mt][k][1], A[mt][k][2], A[mt][k][3],
                        bf1.x, bf1.y);
            }
        }
#pragma unroll
        for (int mt = 0; mt < 4; mt++) {
            AD[mt][0] = h2pack(acc2[mt][0][0], acc2[mt][0][1]);
            AD[mt][1] = h2pack(acc2[mt][0][2], acc2[mt][0][3]);
            AD[mt][2] = h2pack(acc2[mt][1][0], acc2[mt][1][1]);
            AD[mt][3] = h2pack(acc2[mt][1][2], acc2[mt][1][3]);
            int gr0 = base + mrow0 + mt * 16 + g;
#pragma unroll
            for (int h = 0; h < 2; h++) {
                if (gr0 < n)
                    *(float2*)(out + (size_t)gr0 * 16 + h * 8 + 2 * tg) =
                        make_float2(acc2[mt][h][0], acc2[mt][h][1]);
                if (gr0 + 8 < n)
                    *(float2*)(out + (size_t)(gr0 + 8) * 16 + h * 8 + 2 * tg) =
                        make_float2(acc2[mt][h][2], acc2[mt][h][3]);
            }
        }
    }

    // ---- L3: [dens | SH] @ W3 -> A (relu) ----
    {
        uint32_t A3[4][2][4];
#pragma unroll
        for (int mt = 0; mt < 4; mt++) {
            A3[mt][0][0] = AD[mt][0]; A3[mt][0][1] = AD[mt][1];
            A3[mt][0][2] = AD[mt][2]; A3[mt][0][3] = AD[mt][3];
            int r0 = mrow0 + mt * 16 + g;
            A3[mt][1][0] = SH[r0 * SHW + tg];
            A3[mt][1][1] = SH[(r0 + 8) * SHW + tg];
            A3[mt][1][2] = SH[r0 * SHW + 4 + tg];
            A3[mt][1][3] = SH[(r0 + 8) * SHW + 4 + tg];
        }
        layer_pairs<2, 4, 8>(A3, fr + (W3F >> 1), smf + OFF_B3, tg, lane, A);
    }

    // ---- L4: A @ W4 -> A4 (relu) ----
    uint32_t A4[4][4][4];
    layer_pairs<4, 4, 8>(A, fr + (W4F >> 1), smf + OFF_B4, tg, lane, A4);

    // ---- L5: A4 @ W5 -> color (sigmoid) ----
    {
        float acc5[4][4];
#pragma unroll
        for (int mt = 0; mt < 4; mt++) {
            float2 bb = ((const float2*)(smf + OFF_B5))[tg];
            acc5[mt][0] = bb.x; acc5[mt][1] = bb.y;
            acc5[mt][2] = bb.x; acc5[mt][3] = bb.y;
        }
#pragma unroll
        for (int k = 0; k < 4; k++) {
            uint2 bf = fr[(W5F >> 1) + k * 32 + lane];
#pragma unroll
            for (int mt = 0; mt < 4; mt++) {
                float* d4 = acc5[mt];
                float da[4] = {d4[0], d4[1], d4[2], d4[3]};
                mma_f16(reinterpret_cast<float(&)[4]>(*da),
                        A4[mt][k][0], A4[mt][k][1], A4[mt][k][2], A4[mt][k][3],
                        bf.x, bf.y);
                d4[0] = da[0]; d4[1] = da[1]; d4[2] = da[2]; d4[3] = da[3];
            }
        }
        float* co = out + (size_t)n * 16;
#pragma unroll
        for (int mt = 0; mt < 4; mt++) {
            int gr0 = base + mrow0 + mt * 16 + g;
            float s0 = 1.0f / (1.0f + __expf(-acc5[mt][0]));
            float s1 = 1.0f / (1.0f + __expf(-acc5[mt][1]));
            float s2 = 1.0f / (1.0f + __expf(-acc5[mt][2]));
            float s3 = 1.0f / (1.0f + __expf(-acc5[mt][3]));
            if (tg == 0) {
                if (gr0 < n)     { co[(size_t)gr0 * 3 + 0] = s0;
                                   co[(size_t)gr0 * 3 + 1] = s1; }
                if (gr0 + 8 < n) { co[(size_t)(gr0 + 8) * 3 + 0] = s2;
                                   co[(size_t)(gr0 + 8) * 3 + 1] = s3; }
            } else if (tg == 1) {
                if (gr0 < n)     co[(size_t)gr0 * 3 + 2] = s0;
                if (gr0 + 8 < n) co[(size_t)(gr0 + 8) * 3 + 2] = s2;
            }
        }
    }
}

extern "C" void kernel_launch(void* const* d_in, const int* in_sizes, int n_in,
                              void* d_out, int out_size) {
    const float* position = (const float*)d_in[0];
    const float* direction = (const float*)d_in[1];
    const float* W1 = (const float*)d_in[2];
    const float* b1 = (const float*)d_in[3];
    const float* W2 = (const float*)d_in[4];
    const float* b2 = (const float*)d_in[5];
    const float* W3 = (const float*)d_in[6];
    const float* b3 = (const float*)d_in[7];
    const float* W4 = (const float*)d_in[8];
    const float* b4 = (const float*)d_in[9];
    const float* W5 = (const float*)d_in[10];
    const float* b5 = (const float*)d_in[11];
    float* out = (float*)d_out;

    int n = in_sizes[0] / 32;
    int ntiles = (n + ROWS - 1) / ROWS;
    if (ntiles <= 0) return;
    size_t smem_bytes = (size_t)SMEM_WORDS * 4;

    cudaFuncSetAttribute(nerf_mma_kernel,
                         cudaFuncAttributeMaxDynamicSharedMemorySize,
                         (int)smem_bytes);
    prep_kernel<<<20, 256>>>(W1, W2, W3, W4, W5);
    nerf_mma_kernel<<<ntiles, THREADS, smem_bytes>>>(position, direction,
                                                     b1, b2, b3, b4, b5,
                                                     out, n);
}